// round 7
// baseline (speedup 1.0000x reference)
#include <cuda_runtime.h>
#include <cstdint>
#include <math.h>

#define NN   1048576
#define EE   4194304
#define BB   2048
#define DIM  32
#define FXD  55
#define OUTD 128
#define SEQ  1000
#define EMBD 128
#define NF   32
#define KW   8
#define LCONV 121
#define BN_EPS 1e-5f

// ---------------- device scratch (static, allowed) ----------------
__device__ __align__(16) float g_bufA[(size_t)NN * DIM];  // ping (128MB)
__device__ __align__(16) float g_bufB[(size_t)NN * DIM];  // pong (128MB)
__device__ int g_rowoff[NN + 1];
__device__ int g_woff[NN];          // deg, then fill cursor
__device__ int g_csr[EE];
__device__ int g_bsum[1024];
__device__ __align__(16) float g_Wt[SEQ * 256];
__device__ __align__(16) float g_S[(size_t)BB * 26 * 256];
__device__ __align__(16) float g_conv[(size_t)BB * NF * LCONV];
__device__ __align__(16) float g_xj[(size_t)BB * 256];
__device__ __align__(16) float g_z1[(size_t)BB * 1024];
__device__ __align__(16) float g_z2[(size_t)BB * 256];
__device__ __align__(16) float g_pool[(size_t)BB * DIM];
__device__ __align__(16) float g_cnt[BB];
__device__ float g_sum[DIM];
__device__ float g_sq[DIM];
__device__ float g_binv[DIM];
__device__ float g_bsh[DIM];

// ---------------- zero init (small buffers + degree array) ----------------
__global__ void k_zero() {
    int i = blockIdx.x * blockDim.x + threadIdx.x;
    if (i < NN) g_woff[i] = 0;
    if (i < DIM) { g_sum[i] = 0.f; g_sq[i] = 0.f; }
    if (i < BB * DIM) g_pool[i] = 0.f;
    if (i < BB) g_cnt[i] = 0.f;
}

// ---------------- CSR build ----------------
__global__ void k_hist(const int* __restrict__ ei) {
    int e = blockIdx.x * blockDim.x + threadIdx.x;
    if (e >= EE) return;
    int dst = ei[EE + e] & (NN - 1);
    atomicAdd(&g_woff[dst], 1);
}

// block scan: 256 threads x 4 elements = 1024 per block
__global__ void k_scan1() {
    __shared__ int sc[256];
    int t = threadIdx.x;
    int base = blockIdx.x * 1024 + t * 4;
    int d0 = g_woff[base + 0], d1 = g_woff[base + 1];
    int d2 = g_woff[base + 2], d3 = g_woff[base + 3];
    int tsum = d0 + d1 + d2 + d3;
    sc[t] = tsum;
    __syncthreads();
#pragma unroll
    for (int off = 1; off < 256; off <<= 1) {
        int v = (t >= off) ? sc[t - off] : 0;
        __syncthreads();
        sc[t] += v;
        __syncthreads();
    }
    int excl = sc[t] - tsum;
    g_rowoff[base + 0] = excl;
    g_rowoff[base + 1] = excl + d0;
    g_rowoff[base + 2] = excl + d0 + d1;
    g_rowoff[base + 3] = excl + d0 + d1 + d2;
    if (t == 255) g_bsum[blockIdx.x] = sc[255];
}

__global__ void k_scan2() {
    __shared__ int sc[256];
    int t = threadIdx.x;
    int v0 = g_bsum[t * 4 + 0], v1 = g_bsum[t * 4 + 1];
    int v2 = g_bsum[t * 4 + 2], v3 = g_bsum[t * 4 + 3];
    int tsum = v0 + v1 + v2 + v3;
    sc[t] = tsum;
    __syncthreads();
#pragma unroll
    for (int off = 1; off < 256; off <<= 1) {
        int v = (t >= off) ? sc[t - off] : 0;
        __syncthreads();
        sc[t] += v;
        __syncthreads();
    }
    int run = sc[t] - tsum;
    g_bsum[t * 4 + 0] = run;           run += v0;
    g_bsum[t * 4 + 1] = run;           run += v1;
    g_bsum[t * 4 + 2] = run;           run += v2;
    g_bsum[t * 4 + 3] = run;
}

__global__ void k_scan3() {
    int t = threadIdx.x;
    int base = blockIdx.x * 1024 + t * 4;
    int off = g_bsum[blockIdx.x];
#pragma unroll
    for (int k = 0; k < 4; k++) {
        int v = g_rowoff[base + k] + off;
        g_rowoff[base + k] = v;
        g_woff[base + k] = v;
    }
    if (blockIdx.x == 0 && t == 0) g_rowoff[NN] = EE;
}

__global__ void k_fill(const int* __restrict__ ei) {
    int e = blockIdx.x * blockDim.x + threadIdx.x;
    if (e >= EE) return;
    int src = ei[e] & (NN - 1);
    int dst = ei[EE + e] & (NN - 1);
    int pos = atomicAdd(&g_woff[dst], 1);
    g_csr[pos] = src;
}

// ---------------- layer-1 projection: bufA = xd @ w1a ----------------
__global__ void k_proj1(const float* __restrict__ xd, const float* __restrict__ w1a) {
    __shared__ float sWa[FXD * DIM];
    for (int i = threadIdx.x; i < FXD * DIM; i += blockDim.x) sWa[i] = w1a[i];
    __syncthreads();
    long long r = (long long)blockIdx.x * blockDim.x + threadIdx.x;
    if (r >= NN) return;
    float acc[DIM];
#pragma unroll
    for (int j = 0; j < DIM; j++) acc[j] = 0.f;
    const float* xr = xd + r * FXD;
    for (int i = 0; i < FXD; i++) {
        float xi = xr[i];
#pragma unroll
        for (int j = 0; j < DIM; j++) acc[j] += xi * sWa[i * DIM + j];
    }
    float4* ho = (float4*)(g_bufA + r * DIM);
#pragma unroll
    for (int j = 0; j < 8; j++) {
        float4 o;
        o.x = acc[4 * j + 0]; o.y = acc[4 * j + 1];
        o.z = acc[4 * j + 2]; o.w = acc[4 * j + 3];
        ho[j] = o;
    }
}

// ---------------- fused agg + (affine of prev BN) + MLP + stats ----------------
__global__ void __launch_bounds__(256) k_fused(int in_is_B, int use_affine, int has_wa,
                        const float* __restrict__ wa, const float* __restrict__ ba,
                        const float* __restrict__ wb, const float* __restrict__ bb) {
    const float* IN = in_is_B ? g_bufB : g_bufA;
    float* OUT = in_is_B ? g_bufA : g_bufB;
    int lane = threadIdx.x & 31;
    int wid = threadIdx.x >> 5;

    float waCol[32];
    float wbCol[32];
    if (has_wa) {
#pragma unroll
        for (int i = 0; i < 32; i++) waCol[i] = wa[i * 32 + lane];
    }
#pragma unroll
    for (int i = 0; i < 32; i++) wbCol[i] = wb[i * 32 + lane];
    float baj = ba[lane];
    float bbj = bb[lane];
    float binvj = use_affine ? g_binv[lane] : 1.f;
    float bshj  = use_affine ? g_bsh[lane]  : 0.f;

    float sj = 0.f, qj = 0.f;
    int gw = blockIdx.x * 8 + wid;
    int nwarps = gridDim.x * 8;
    for (int node = gw; node < NN; node += nwarps) {
        int beg = g_rowoff[node];
        int end = g_rowoff[node + 1];
        float acc = IN[(long long)node * 32 + lane];
        for (int p = beg; p < end; p++) {
            int s = g_csr[p];
            acc += IN[(long long)s * 32 + lane];
        }
        float xin = binvj * acc + (float)(end - beg + 1) * bshj;
        float gj;
        if (has_wa) {
            gj = baj;
#pragma unroll
            for (int i = 0; i < 32; i++)
                gj += __shfl_sync(0xffffffffu, xin, i) * waCol[i];
        } else {
            gj = xin + baj;
        }
        gj = fmaxf(gj, 0.f);
        float mj = bbj;
#pragma unroll
        for (int i = 0; i < 32; i++)
            mj += __shfl_sync(0xffffffffu, gj, i) * wbCol[i];
        mj = fmaxf(mj, 0.f);
        OUT[(long long)node * 32 + lane] = mj;
        sj += mj;
        qj += mj * mj;
    }
    __shared__ float sS[32];
    __shared__ float sQ[32];
    if (threadIdx.x < 32) { sS[threadIdx.x] = 0.f; sQ[threadIdx.x] = 0.f; }
    __syncthreads();
    atomicAdd(&sS[lane], sj);
    atomicAdd(&sQ[lane], qj);
    __syncthreads();
    if (threadIdx.x < 32) {
        atomicAdd(&g_sum[threadIdx.x], sS[threadIdx.x]);
        atomicAdd(&g_sq[threadIdx.x], sQ[threadIdx.x]);
    }
}

__global__ void k_bnfin(const float* __restrict__ bng, const float* __restrict__ bnb, int layer) {
    int j = threadIdx.x;
    if (j >= DIM) return;
    float s = g_sum[j], ss = g_sq[j];
    float mu = s / (float)NN;
    float var = ss / (float)NN - mu * mu;
    float inv = bng[layer * DIM + j] * rsqrtf(var + BN_EPS);
    g_binv[j] = inv;
    g_bsh[j] = bnb[layer * DIM + j] - mu * inv;
    g_sum[j] = 0.f; g_sq[j] = 0.f;
}

// ---------------- pool with fused final affine; m5 lives in g_bufB ----------------
__global__ void k_pool(const int* __restrict__ batch) {
    long long t = (long long)blockIdx.x * blockDim.x + threadIdx.x;
    if (t >= (long long)NN * 8) return;
    long long node = t >> 3;
    int q = (int)(t & 7);
    float4 v = ((const float4*)g_bufB)[t];
    float4 o;
    o.x = v.x * g_binv[q * 4 + 0] + g_bsh[q * 4 + 0];
    o.y = v.y * g_binv[q * 4 + 1] + g_bsh[q * 4 + 1];
    o.z = v.z * g_binv[q * 4 + 2] + g_bsh[q * 4 + 2];
    o.w = v.w * g_binv[q * 4 + 3] + g_bsh[q * 4 + 3];
    int g = batch[node] & (BB - 1);
    float* pp = g_pool + (long long)g * DIM + q * 4;
    atomicAdd(pp + 0, o.x);
    atomicAdd(pp + 1, o.y);
    atomicAdd(pp + 2, o.z);
    atomicAdd(pp + 3, o.w);
    if (q == 0) atomicAdd(&g_cnt[g], 1.f);
}

// xdv = relu(pooled/cnt @ fcd_w + fcd_b) -> g_xj[:, 0:128]
__global__ void k_xdv(const float* __restrict__ fcd_w, const float* __restrict__ fcd_b) {
    __shared__ float sp[DIM];
    int b = blockIdx.x;
    if (threadIdx.x < DIM) {
        float c = g_cnt[b];
        sp[threadIdx.x] = g_pool[(long long)b * DIM + threadIdx.x] / fmaxf(c, 1.f);
    }
    __syncthreads();
    int o = threadIdx.x;  // 128 threads
    float acc = fcd_b[o];
#pragma unroll
    for (int i = 0; i < DIM; i++) acc += sp[i] * fcd_w[i * OUTD + o];
    g_xj[(long long)b * 256 + o] = fmaxf(acc, 0.f);
}

// ---------------- protein branch ----------------
__global__ void k_wt(const float* __restrict__ conv_w) {
    int t = blockIdx.x * blockDim.x + threadIdx.x;
    if (t >= SEQ * 256) return;
    int c = t >> 8;
    int fk = t & 255;
    int f = fk >> 3, k = fk & 7;
    g_Wt[t] = conv_w[(f * SEQ + c) * KW + k];
}

__global__ void k_bucketS(const int* __restrict__ xt) {
    __shared__ int cnt[26];
    __shared__ int off[27];
    __shared__ int woff[26];
    __shared__ unsigned short perm[SEQ];
    int b = blockIdx.x;
    int tid = threadIdx.x;
    if (tid < 26) cnt[tid] = 0;
    __syncthreads();
    const int* xr = xt + (long long)b * SEQ;
    for (int c = tid; c < SEQ; c += 256) {
        int v = xr[c]; v = v < 0 ? 0 : (v > 25 ? 25 : v);
        atomicAdd(&cnt[v], 1);
    }
    __syncthreads();
    if (tid == 0) {
        int a = 0;
        for (int v = 0; v < 26; v++) { off[v] = a; a += cnt[v]; }
        off[26] = a;
    }
    __syncthreads();
    if (tid < 26) woff[tid] = off[tid];
    __syncthreads();
    for (int c = tid; c < SEQ; c += 256) {
        int v = xr[c]; v = v < 0 ? 0 : (v > 25 ? 25 : v);
        int p = atomicAdd(&woff[v], 1);
        perm[p] = (unsigned short)c;
    }
    __syncthreads();
    int fk = tid;
    float* So = g_S + (long long)b * 26 * 256;
    for (int v = 0; v < 26; v++) {
        float acc = 0.f;
        int e = off[v + 1];
        for (int i = off[v]; i < e; i++)
            acc += g_Wt[(int)perm[i] * 256 + fk];
        So[v * 256 + fk] = acc;
    }
}

__global__ void k_conv(const float* __restrict__ emb, const float* __restrict__ conv_b) {
    __shared__ float sS[26 * 256];
    __shared__ float sE[26 * EMBD];
    int b = blockIdx.x;
    int tid = threadIdx.x;
    const float* Sb = g_S + (long long)b * 26 * 256;
    for (int i = tid; i < 26 * 256; i += 256) sS[i] = Sb[i];
    for (int i = tid; i < 26 * EMBD; i += 256) sE[i] = emb[i];
    __syncthreads();
    int f = tid >> 3;
    int sub = tid & 7;
    int hh0 = sub * 16;
    int nh = LCONV - hh0; if (nh > 16) nh = 16;
    float cb = conv_b[f];
    float acc[16];
#pragma unroll
    for (int j = 0; j < 16; j++) acc[j] = cb;
    for (int v = 0; v < 26; v++) {
        float sk[8];
#pragma unroll
        for (int k = 0; k < 8; k++) sk[k] = sS[v * 256 + f * 8 + k];
        float ev[23];
#pragma unroll
        for (int j = 0; j < 23; j++) ev[j] = (j < nh + 7) ? sE[v * EMBD + hh0 + j] : 0.f;
#pragma unroll
        for (int j = 0; j < 16; j++) {
            if (j < nh) {
                float a = acc[j];
#pragma unroll
                for (int k = 0; k < 8; k++) a += sk[k] * ev[j + k];
                acc[j] = a;
            }
        }
    }
    for (int j = 0; j < nh; j++)
        g_conv[(long long)b * (NF * LCONV) + f * LCONV + hh0 + j] = acc[j];
}

// ---------------- generic tiled GEMM with device-side buffer selection ----------------
// a_id: 0=g_conv 1=g_xj 2=g_z1 ; c_id: 0=g_xj+128 1=g_z1 2=g_z2
__global__ void k_gemm(int a_id, int lda,
                       const float* __restrict__ W, const float* __restrict__ bias,
                       int c_id, int ldc, int K, int N2, int dorelu) {
    const float* A = (a_id == 0) ? g_conv : (a_id == 1) ? g_xj : g_z1;
    float* C = (c_id == 0) ? (g_xj + 128) : (c_id == 1) ? g_z1 : g_z2;
    __shared__ float As[16][33];
    int m0 = blockIdx.x * 16;
    int n0 = blockIdx.y * 128;
    int col = threadIdx.x & 127;
    int rg = threadIdx.x >> 7;
    float acc[8];
#pragma unroll
    for (int r = 0; r < 8; r++) acc[r] = 0.f;
    for (int k0 = 0; k0 < K; k0 += 32) {
#pragma unroll
        for (int l = 0; l < 2; l++) {
            int idx = threadIdx.x + 256 * l;
            int rr = idx >> 5, kk = idx & 31;
            As[rr][kk] = A[(long long)(m0 + rr) * lda + k0 + kk];
        }
        __syncthreads();
#pragma unroll 8
        for (int kk = 0; kk < 32; kk++) {
            float w = W[(long long)(k0 + kk) * N2 + n0 + col];
#pragma unroll
            for (int r = 0; r < 8; r++) acc[r] += As[rg * 8 + r][kk] * w;
        }
        __syncthreads();
    }
    float bv = bias[n0 + col];
#pragma unroll
    for (int r = 0; r < 8; r++) {
        float v = acc[r] + bv;
        if (dorelu) v = fmaxf(v, 0.f);
        C[(long long)(m0 + rg * 8 + r) * ldc + n0 + col] = v;
    }
}

__global__ void k_final(const float* __restrict__ c3w, const float* __restrict__ c3b,
                        float* __restrict__ out) {
    int gwarp = (blockIdx.x * blockDim.x + threadIdx.x) >> 5;
    int lane = threadIdx.x & 31;
    if (gwarp >= BB) return;
    float acc = 0.f;
    for (int i = lane; i < 256; i += 32) acc += g_z2[(long long)gwarp * 256 + i] * c3w[i];
#pragma unroll
    for (int s = 16; s > 0; s >>= 1) acc += __shfl_down_sync(0xffffffffu, acc, s);
    if (lane == 0) out[gwarp] = acc + c3b[0];
}

// ---------------- launch ----------------
extern "C" void kernel_launch(void* const* d_in, const int* in_sizes, int n_in,
                              void* d_out, int out_size) {
    (void)in_sizes; (void)n_in; (void)out_size;
    const float* xd    = (const float*)d_in[0];
    const int*   ei    = (const int*)d_in[1];
    const int*   batch = (const int*)d_in[2];
    const int*   xt    = (const int*)d_in[3];
    const float* w1a = (const float*)d_in[4];
    const float* b1a = (const float*)d_in[5];
    const float* w1b = (const float*)d_in[6];
    const float* b1b = (const float*)d_in[7];
    const float* wa  = (const float*)d_in[8];
    const float* ba  = (const float*)d_in[9];
    const float* wb  = (const float*)d_in[10];
    const float* bb  = (const float*)d_in[11];
    const float* bng = (const float*)d_in[12];
    const float* bnb = (const float*)d_in[13];
    const float* fcd_w = (const float*)d_in[14];
    const float* fcd_b = (const float*)d_in[15];
    const float* emb   = (const float*)d_in[16];
    const float* conv_w = (const float*)d_in[17];
    const float* conv_b = (const float*)d_in[18];
    const float* fct_w  = (const float*)d_in[19];
    const float* fct_b  = (const float*)d_in[20];
    const float* c1w = (const float*)d_in[21];
    const float* c1b = (const float*)d_in[22];
    const float* c2w = (const float*)d_in[23];
    const float* c2b = (const float*)d_in[24];
    const float* c3w = (const float*)d_in[25];
    const float* c3b = (const float*)d_in[26];
    float* out = (float*)d_out;

    const int T = 256;

    // init + CSR build
    k_zero<<<(NN + T - 1) / T, T>>>();
    k_hist<<<(EE + T - 1) / T, T>>>(ei);
    k_scan1<<<1024, 256>>>();
    k_scan2<<<1, 256>>>();
    k_scan3<<<1024, 256>>>();
    k_fill<<<(EE + T - 1) / T, T>>>(ei);

    // ---- protein branch ----
    k_wt<<<(SEQ * 256 + T - 1) / T, T>>>(conv_w);
    k_bucketS<<<BB, 256>>>(xt);
    k_conv<<<BB, 256>>>(emb, conv_b);
    {
        dim3 grid(BB / 16, OUTD / 128);
        k_gemm<<<grid, 256>>>(0, NF * LCONV, fct_w, fct_b, 0, 256, NF * LCONV, OUTD, 0);
    }

    // ---- graph branch ----
    const int FB = 8192;  // fused grid blocks
    k_proj1<<<(NN + T - 1) / T, T>>>(xd, w1a);
    // L1: in A -> out B (no affine, no Wa)
    k_fused<<<FB, 256>>>(0, 0, 0, nullptr, b1a, w1b, b1b);
    k_bnfin<<<1, 32>>>(bng, bnb, 0);
    // L2..L5 ping-pong: B->A->B->A->B
    for (int l = 0; l < 4; l++) {
        int in_is_B = (l % 2 == 0) ? 1 : 0;
        k_fused<<<FB, 256>>>(in_is_B, 1, 1,
                             wa + (size_t)l * DIM * DIM, ba + (size_t)l * DIM,
                             wb + (size_t)l * DIM * DIM, bb + (size_t)l * DIM);
        k_bnfin<<<1, 32>>>(bng, bnb, l + 1);
    }
    // m5 is in g_bufB; pool applies layer-5 affine
    k_pool<<<((long long)NN * 8 + T - 1) / T, T>>>(batch);
    k_xdv<<<BB, 128>>>(fcd_w, fcd_b);

    // ---- classifier ----
    {
        dim3 g1(BB / 16, 1024 / 128);
        k_gemm<<<g1, 256>>>(1, 256, c1w, c1b, 1, 1024, 256, 1024, 1);
        dim3 g2(BB / 16, 256 / 128);
        k_gemm<<<g2, 256>>>(2, 1024, c2w, c2b, 2, 256, 1024, 256, 1);
    }
    k_final<<<(BB * 32 + T - 1) / T, T>>>(c3w, c3b, out);
}